// round 2
// baseline (speedup 1.0000x reference)
#include <cuda_runtime.h>

// CapsuleLayer dynamic routing, fully fused into 3 streaming passes + 3 tiny
// squash kernels. Key identity: b_ij after r rounds = u_hat · (v_0+...+v_{r-1}),
// so u_hat never needs to be materialized; it is recomputed per pass from W
// (75.5 MB) instead of storing/re-reading 302 MB.

#define BB 32      // batch
#define JJ 32      // output capsules
#define II 4608    // input capsules
#define DA 8       // d_in
#define DD 16      // d_out
#define CHUNK 32   // i per CTA
#define NCHUNK 144 // 144*32 = 4608
#define CAP_EPS 1e-7f

// scratch (no allocations allowed)
__device__ float g_partial[NCHUNK * BB * JJ * DD]; // per-chunk partial s  (9.4 MB)
__device__ float g_vsum[BB * JJ * DD];             // v0, then v0+v1

// ---------------------------------------------------------------------------
// Pass kernel: grid = NCHUNK CTAs (one 32-i chunk each, all 32 batches),
// block = 512 threads = 16 warps. lane = j (0..31), warp w handles b = 2w,2w+1.
// Shared (dynamic, 49152 B):
//   [0,4096)    W tile buf0   (j*128 + ((8d+a) ^ (j&31)))  XOR-swizzled
//   [4096,8192) W tile buf1
//   [8192,12288) inputs half-chunk: [b][il&15][a] = b*128 + ih*8 + a
// ---------------------------------------------------------------------------
template <int PASS>
__global__ void __launch_bounds__(512, 1)
pass_kernel(const float* __restrict__ xg, const float* __restrict__ Wg) {
    extern __shared__ float sh[];
    float* xsh = sh + 8192;

    const int t    = threadIdx.x;
    const int j    = t & 31;       // lane = output capsule
    const int w    = t >> 5;       // warp id
    const int jlo  = j & 7;
    const int jmid = j & 24;
    const int b0   = 2 * w;
    const int b1   = b0 + 1;
    const int i0   = blockIdx.x * CHUNK;
    const int trow = t >> 7;       // 0..3 (W copy row group)
    const int tda  = t & 127;      // W copy column

    // v history in registers (tiny, L2-hot)
    float v0r[DD], v1r[DD];
    if (PASS > 0) {
#pragma unroll
        for (int d = 0; d < DD; d++) {
            v0r[d] = g_vsum[(b0 * JJ + j) * DD + d];
            v1r[d] = g_vsum[(b1 * JJ + j) * DD + d];
        }
    }

    // inputs, first half of chunk (i0 .. i0+15): contiguous per b in global
    for (int idx = t; idx < 4096; idx += 512) {
        int b = idx >> 7;
        xsh[idx] = xg[b * (II * DA) + i0 * DA + (idx & 127)];
    }

    // W tile prefetch pipeline. Tile for capsule-row jr, position i is the
    // 128 contiguous floats Wg[(jr*II + i)*128 + da]. Swizzled store:
    // phys = jr*128 + (da ^ (jr & 31))  -> conflict-free store AND read.
    float wreg[8];
#pragma unroll
    for (int k = 0; k < 8; k++) {
        int jr = k * 4 + trow;
        wreg[k] = Wg[(jr * II + i0) * 128 + tda];
    }
#pragma unroll
    for (int k = 0; k < 8; k++) {
        int jr = k * 4 + trow;
        sh[jr * 128 + (tda ^ (jr & 31))] = wreg[k];  // buf0
    }
#pragma unroll
    for (int k = 0; k < 8; k++) {
        int jr = k * 4 + trow;
        wreg[k] = Wg[(jr * II + (i0 + 1)) * 128 + tda];
    }
    __syncthreads();

    float acc0[DD], acc1[DD];
#pragma unroll
    for (int d = 0; d < DD; d++) { acc0[d] = 0.f; acc1[d] = 0.f; }

    for (int il = 0; il < CHUNK; ++il) {
        if (il == 16) {  // second half of inputs (readers of half 0 all past last sync)
            for (int idx = t; idx < 4096; idx += 512) {
                int b = idx >> 7;
                xsh[idx] = xg[b * (II * DA) + i0 * DA + 128 + (idx & 127)];
            }
            __syncthreads();
        }

        const float* wb = sh + ((il & 1) << 12) + j * 128;

        // u_hat[b, j(=lane), i0+il, :] for both b's; W value reused across b.
        float u0[DD], u1[DD];
#pragma unroll
        for (int d = 0; d < DD; d++) { u0[d] = 0.f; u1[d] = 0.f; }
#pragma unroll
        for (int a = 0; a < DA; a++) {
            float x0 = xsh[b0 * 128 + (il & 15) * 8 + a];  // broadcast LDS
            float x1 = xsh[b1 * 128 + (il & 15) * 8 + a];
            const int ax = a ^ jlo;
#pragma unroll
            for (int d = 0; d < DD; d++) {
                float wv = wb[((d * 8) ^ jmid) + ax];      // conflict-free LDS
                u0[d] = fmaf(wv, x0, u0[d]);
                u1[d] = fmaf(wv, x1, u1[d]);
            }
        }

        if (PASS == 0) {
            // c = softmax(0) = 1/32 uniform; scale folded into squash round 0.
#pragma unroll
            for (int d = 0; d < DD; d++) { acc0[d] += u0[d]; acc1[d] += u1[d]; }
        } else {
            float l0 = 0.f, l1 = 0.f;
#pragma unroll
            for (int d = 0; d < DD; d++) {
                l0 = fmaf(u0[d], v0r[d], l0);
                l1 = fmaf(u1[d], v1r[d], l1);
            }
            // softmax over j = pure intra-warp butterfly (lanes are all 32 j's)
            float m0 = l0, m1 = l1;
#pragma unroll
            for (int off = 16; off > 0; off >>= 1) {
                m0 = fmaxf(m0, __shfl_xor_sync(0xffffffffu, m0, off));
                m1 = fmaxf(m1, __shfl_xor_sync(0xffffffffu, m1, off));
            }
            float e0 = __expf(l0 - m0), e1 = __expf(l1 - m1);
            float z0 = e0, z1 = e1;
#pragma unroll
            for (int off = 16; off > 0; off >>= 1) {
                z0 += __shfl_xor_sync(0xffffffffu, z0, off);
                z1 += __shfl_xor_sync(0xffffffffu, z1, off);
            }
            float c0 = __fdividef(e0, z0), c1 = __fdividef(e1, z1);
#pragma unroll
            for (int d = 0; d < DD; d++) {
                acc0[d] = fmaf(c0, u0[d], acc0[d]);
                acc1[d] = fmaf(c1, u1[d], acc1[d]);
            }
        }

        // stage next W tile (writes the buffer last READ in iter il-1 -> safe)
        if (il + 1 < CHUNK) {
            float* dst = sh + (((il + 1) & 1) << 12);
#pragma unroll
            for (int k = 0; k < 8; k++) {
                int jr = k * 4 + trow;
                dst[jr * 128 + (tda ^ (jr & 31))] = wreg[k];
            }
            if (il + 2 < CHUNK) {
#pragma unroll
                for (int k = 0; k < 8; k++) {
                    int jr = k * 4 + trow;
                    wreg[k] = Wg[(jr * II + (i0 + il + 2)) * 128 + tda];
                }
            }
            __syncthreads();
        }
    }

    // deterministic two-stage reduction: per-chunk partials, reduced in squash
    float* p0 = &g_partial[((blockIdx.x * BB + b0) * JJ + j) * DD];
    float* p1 = &g_partial[((blockIdx.x * BB + b1) * JJ + j) * DD];
#pragma unroll
    for (int d = 0; d < DD; d++) { p0[d] = acc0[d]; p1[d] = acc1[d]; }
}

// ---------------------------------------------------------------------------
// Squash: one thread per (b,j,d) output element. Sums NCHUNK partials with
// 4-way ILP (L2-resident), then 16-lane shfl reduction for |s|^2.
// ---------------------------------------------------------------------------
template <int ROUND>
__global__ void __launch_bounds__(256)
squash_kernel(float* __restrict__ out) {
    int tid = blockIdx.x * 256 + threadIdx.x;  // = (b*JJ + j)*DD + d
    const float* p = g_partial + tid;
    float s0 = 0.f, s1 = 0.f, s2 = 0.f, s3 = 0.f;
#pragma unroll 4
    for (int c = 0; c < NCHUNK; c += 4) {
        s0 += p[(c + 0) * (BB * JJ * DD)];
        s1 += p[(c + 1) * (BB * JJ * DD)];
        s2 += p[(c + 2) * (BB * JJ * DD)];
        s3 += p[(c + 3) * (BB * JJ * DD)];
    }
    float s = (s0 + s1) + (s2 + s3);
    if (ROUND == 0) s *= 0.03125f;  // uniform c = 1/32 folded here

    float sq = s * s;  // lanes d=0..15 form aligned 16-groups within the warp
#pragma unroll
    for (int off = 8; off > 0; off >>= 1)
        sq += __shfl_xor_sync(0xffffffffu, sq, off);

    float v = s * (sq / ((1.0f + sq) * sqrtf(sq + CAP_EPS)));

    if (ROUND == 0)      g_vsum[tid] = v;        // v0
    else if (ROUND == 1) g_vsum[tid] += v;       // v0 + v1
    else                 out[tid] = v;           // final v2 -> d_out
}

// ---------------------------------------------------------------------------
extern "C" void kernel_launch(void* const* d_in, const int* in_sizes, int n_in,
                              void* d_out, int out_size) {
    (void)in_sizes; (void)n_in; (void)out_size;
    const float* xg = (const float*)d_in[0];   // inputs [32,4608,8]
    const float* Wg = (const float*)d_in[1];   // W      [32,4608,16,8]
    float* out = (float*)d_out;                // [32,32,16]

    const int SMEM = 49152;  // 48 KB: within default dynamic limit, no attribute needed

    pass_kernel<0><<<NCHUNK, 512, SMEM>>>(xg, Wg);
    squash_kernel<0><<<64, 256>>>(out);
    pass_kernel<1><<<NCHUNK, 512, SMEM>>>(xg, Wg);
    squash_kernel<1><<<64, 256>>>(out);
    pass_kernel<2><<<NCHUNK, 512, SMEM>>>(xg, Wg);
    squash_kernel<2><<<64, 256>>>(out);
}

// round 3
// speedup vs baseline: 1.5470x; 1.5470x over previous
#include <cuda_runtime.h>

// CapsuleLayer dynamic routing: 3 streaming passes (u_hat recomputed from W,
// never materialized) + 3 tiny squash kernels.
// R2: 4 batches/warp (halves W shared traffic), packed fma.rn.f32x2 over
// d-pairs (halves FMA instr count) with W transposed to [a][d] in shared.

#define BB 32
#define JJ 32
#define II 4608
#define DA 8
#define DD 16
#define CHUNK 32
#define NCHUNK 144
#define CAP_EPS 1e-7f

typedef unsigned long long u64;

__device__ float g_partial[NCHUNK * BB * JJ * DD]; // per-chunk partial s (9.4 MB)
__device__ float g_vsum[BB * JJ * DD];             // v0, then v0+v1

__device__ __forceinline__ u64 pack2(float x, float y) {
    u64 r; asm("mov.b64 %0, {%1, %2};" : "=l"(r) : "f"(x), "f"(y)); return r;
}
__device__ __forceinline__ void unpack2(u64 v, float& x, float& y) {
    asm("mov.b64 {%0, %1}, %2;" : "=f"(x), "=f"(y) : "l"(v));
}
__device__ __forceinline__ u64 ffma2(u64 a, u64 b, u64 c) {
    u64 d; asm("fma.rn.f32x2 %0, %1, %2, %3;" : "=l"(d) : "l"(a), "l"(b), "l"(c)); return d;
}

// ---------------------------------------------------------------------------
// Pass kernel: 144 CTAs (one 32-i chunk, all 32 batches), 256 threads = 8 warps.
// lane = j; warp w owns batches 4w..4w+3.
// Shared (49152 B):
//   [0,4096)     W tile buf0, transposed per (j): float z = a*16+d at
//                phys = j*128 + ((z>>2) ^ j)*4 + (z&3)   (float4-XOR swizzle)
//   [4096,8192)  W tile buf1
//   [8192,12288) x half-chunk: xsh[b*128 + (il&15)*8 + a]
// ---------------------------------------------------------------------------
template <int PASS>
__global__ void __launch_bounds__(256, 1)
pass_kernel(const float* __restrict__ xg, const float* __restrict__ Wg) {
    extern __shared__ float sh[];
    float* xsh = sh + 8192;
    const float4* Wg4 = (const float4*)Wg;

    const int t  = threadIdx.x;
    const int j  = t & 31;         // lane = output capsule
    const int w  = t >> 5;         // warp 0..7
    const int b0 = w * 4;
    const int i0 = blockIdx.x * CHUNK;
    // staging mapping: thread -> (row sj, f), 4 float4 global loads, 16 STS
    const int sj   = t >> 3;       // 0..31 (j row staged)
    const int sf   = t & 7;
    const int ssub = sf >> 1;
    const int sq0  = (sf & 1) << 4;

    // v history (PASS>0) packed as (v[2dp], v[2dp+1])
    u64 v2[4][DD / 2];
    if (PASS > 0) {
#pragma unroll
        for (int bi = 0; bi < 4; bi++) {
            const u64* vp = (const u64*)&g_vsum[((b0 + bi) * JJ + j) * DD];
#pragma unroll
            for (int dp = 0; dp < DD / 2; dp++) v2[bi][dp] = vp[dp];
        }
    }

    // x first half (i0..i0+15)
    for (int idx = t; idx < 4096; idx += 256) {
        int b = idx >> 7;
        xsh[idx] = xg[b * (II * DA) + i0 * DA + (idx & 127)];
    }

    // W staging pipeline (transpose + swizzle). Tile = 4096 floats.
    float4 g[4];
#pragma unroll
    for (int k = 0; k < 4; k++)
        g[k] = Wg4[(sj * II + i0) * 32 + k * 8 + sf];
    {
        float* row = sh + sj * 128;
#pragma unroll
        for (int k = 0; k < 4; k++) {
            row[((sq0 + 0  + k) ^ sj) * 4 + ssub] = g[k].x;
            row[((sq0 + 4  + k) ^ sj) * 4 + ssub] = g[k].y;
            row[((sq0 + 8  + k) ^ sj) * 4 + ssub] = g[k].z;
            row[((sq0 + 12 + k) ^ sj) * 4 + ssub] = g[k].w;
        }
    }
#pragma unroll
    for (int k = 0; k < 4; k++)
        g[k] = Wg4[(sj * II + (i0 + 1)) * 32 + k * 8 + sf];
    __syncthreads();

    u64 acc2[4][DD / 2];
#pragma unroll
    for (int bi = 0; bi < 4; bi++)
#pragma unroll
        for (int dp = 0; dp < DD / 2; dp++) acc2[bi][dp] = 0ull;

    for (int il = 0; il < CHUNK; ++il) {
        if (il == 16) {  // second half of x; all readers of half 0 passed iter-15 sync
            for (int idx = t; idx < 4096; idx += 256) {
                int b = idx >> 7;
                xsh[idx] = xg[b * (II * DA) + i0 * DA + 128 + (idx & 127)];
            }
            __syncthreads();
        }

        const ulonglong2* wb = (const ulonglong2*)(sh + ((il & 1) << 12) + j * 128);
        const float* xb = xsh + (il & 15) * 8;

        u64 u2[4][DD / 2];
        if (PASS > 0) {
#pragma unroll
            for (int bi = 0; bi < 4; bi++)
#pragma unroll
                for (int dp = 0; dp < DD / 2; dp++) u2[bi][dp] = 0ull;
        }

#pragma unroll
        for (int a = 0; a < DA; a++) {
            u64 xx[4];
#pragma unroll
            for (int bi = 0; bi < 4; bi++) {
                float xv = xb[(b0 + bi) * 128 + a];   // broadcast LDS
                xx[bi] = pack2(xv, xv);
            }
#pragma unroll
            for (int d4 = 0; d4 < 4; d4++) {
                // float4 = W[a][4d4..4d4+3] for this j, conflict-free LDS.128
                ulonglong2 wv = wb[((a << 2) | d4) ^ j];
#pragma unroll
                for (int bi = 0; bi < 4; bi++) {
                    if (PASS == 0) {  // uniform c folded into squash: accumulate directly
                        acc2[bi][2 * d4]     = ffma2(wv.x, xx[bi], acc2[bi][2 * d4]);
                        acc2[bi][2 * d4 + 1] = ffma2(wv.y, xx[bi], acc2[bi][2 * d4 + 1]);
                    } else {
                        u2[bi][2 * d4]     = ffma2(wv.x, xx[bi], u2[bi][2 * d4]);
                        u2[bi][2 * d4 + 1] = ffma2(wv.y, xx[bi], u2[bi][2 * d4 + 1]);
                    }
                }
            }
        }

        if (PASS > 0) {
#pragma unroll
            for (int bi = 0; bi < 4; bi++) {
                u64 lp = 0ull;
#pragma unroll
                for (int dp = 0; dp < DD / 2; dp++)
                    lp = ffma2(u2[bi][dp], v2[bi][dp], lp);
                float lo, hi; unpack2(lp, lo, hi);
                float l = lo + hi;
                // softmax over j = lanes; |l| small -> skip max-subtract
                float e = __expf(l);
                float z = e;
#pragma unroll
                for (int off = 16; off > 0; off >>= 1)
                    z += __shfl_xor_sync(0xffffffffu, z, off);
                float c = __fdividef(e, z);
                u64 cc = pack2(c, c);
#pragma unroll
                for (int dp = 0; dp < DD / 2; dp++)
                    acc2[bi][dp] = ffma2(cc, u2[bi][dp], acc2[bi][dp]);
            }
        }

        // stage next tile into the buffer last read at il-1 (safe: past that sync)
        if (il + 1 < CHUNK) {
            float* row = sh + (((il + 1) & 1) << 12) + sj * 128;
#pragma unroll
            for (int k = 0; k < 4; k++) {
                row[((sq0 + 0  + k) ^ sj) * 4 + ssub] = g[k].x;
                row[((sq0 + 4  + k) ^ sj) * 4 + ssub] = g[k].y;
                row[((sq0 + 8  + k) ^ sj) * 4 + ssub] = g[k].z;
                row[((sq0 + 12 + k) ^ sj) * 4 + ssub] = g[k].w;
            }
            if (il + 2 < CHUNK) {
#pragma unroll
                for (int k = 0; k < 4; k++)
                    g[k] = Wg4[(sj * II + (i0 + il + 2)) * 32 + k * 8 + sf];
            }
            __syncthreads();
        }
    }

    // per-chunk partials (deterministic two-stage reduction)
#pragma unroll
    for (int bi = 0; bi < 4; bi++) {
        u64* p = (u64*)&g_partial[((blockIdx.x * BB + (b0 + bi)) * JJ + j) * DD];
#pragma unroll
        for (int dp = 0; dp < DD / 2; dp++) p[dp] = acc2[bi][dp];
    }
}

// ---------------------------------------------------------------------------
// Squash: one thread per (b,j,d). 8-way ILP over the 144 chunk partials.
// ---------------------------------------------------------------------------
template <int ROUND>
__global__ void __launch_bounds__(256)
squash_kernel(float* __restrict__ out) {
    int tid = blockIdx.x * 256 + threadIdx.x;  // (b*JJ + j)*DD + d
    const float* p = g_partial + tid;
    float s0 = 0.f, s1 = 0.f, s2 = 0.f, s3 = 0.f;
    float s4 = 0.f, s5 = 0.f, s6 = 0.f, s7 = 0.f;
#pragma unroll
    for (int c = 0; c < NCHUNK; c += 8) {
        s0 += p[(c + 0) * (BB * JJ * DD)];
        s1 += p[(c + 1) * (BB * JJ * DD)];
        s2 += p[(c + 2) * (BB * JJ * DD)];
        s3 += p[(c + 3) * (BB * JJ * DD)];
        s4 += p[(c + 4) * (BB * JJ * DD)];
        s5 += p[(c + 5) * (BB * JJ * DD)];
        s6 += p[(c + 6) * (BB * JJ * DD)];
        s7 += p[(c + 7) * (BB * JJ * DD)];
    }
    float s = ((s0 + s1) + (s2 + s3)) + ((s4 + s5) + (s6 + s7));
    if (ROUND == 0) s *= 0.03125f;  // uniform c = 1/32 folded here

    float sq = s * s;  // lanes d=0..15 form aligned 16-groups within the warp
#pragma unroll
    for (int off = 8; off > 0; off >>= 1)
        sq += __shfl_xor_sync(0xffffffffu, sq, off);

    float v = s * (sq / ((1.0f + sq) * sqrtf(sq + CAP_EPS)));

    if (ROUND == 0)      g_vsum[tid] = v;
    else if (ROUND == 1) g_vsum[tid] += v;
    else                 out[tid] = v;
}

// ---------------------------------------------------------------------------
extern "C" void kernel_launch(void* const* d_in, const int* in_sizes, int n_in,
                              void* d_out, int out_size) {
    (void)in_sizes; (void)n_in; (void)out_size;
    const float* xg = (const float*)d_in[0];   // inputs [32,4608,8]
    const float* Wg = (const float*)d_in[1];   // W      [32,4608,16,8]
    float* out = (float*)d_out;                // [32,32,16]

    const int SMEM = 49152;

    pass_kernel<0><<<NCHUNK, 256, SMEM>>>(xg, Wg);
    squash_kernel<0><<<64, 256>>>(out);
    pass_kernel<1><<<NCHUNK, 256, SMEM>>>(xg, Wg);
    squash_kernel<1><<<64, 256>>>(out);
    pass_kernel<2><<<NCHUNK, 256, SMEM>>>(xg, Wg);
    squash_kernel<2><<<64, 256>>>(out);
}

// round 4
// speedup vs baseline: 1.6182x; 1.0460x over previous
#include <cuda_runtime.h>

// CapsuleLayer dynamic routing: 3 streaming passes (u_hat recomputed from W,
// never materialized; b_ij == u_hat·(v0+..+v_{r-1})) + 3 squash kernels.
// R3: 4-slot W ring in 96KB smem -> barrier every 2 i (softmax chain hidden
// under next-i FMA stream); full-chunk x loaded once; squash with 4-way
// chunk-split and 1024-thread CTAs.

#define BB 32
#define JJ 32
#define II 4608
#define DA 8
#define DD 16
#define CHUNK 32
#define NCHUNK 144
#define OUTSZ (BB * JJ * DD)        // 16384
#define CAP_EPS 1e-7f

typedef unsigned long long u64;

__device__ float g_partial[NCHUNK * OUTSZ]; // per-chunk partial s (9.4 MB)
__device__ float g_vsum[OUTSZ];             // v0, then v0+v1

__device__ __forceinline__ u64 pack2(float x, float y) {
    u64 r; asm("mov.b64 %0, {%1, %2};" : "=l"(r) : "f"(x), "f"(y)); return r;
}
__device__ __forceinline__ void unpack2(u64 v, float& x, float& y) {
    asm("mov.b64 {%0, %1}, %2;" : "=f"(x), "=f"(y) : "l"(v));
}
__device__ __forceinline__ u64 ffma2(u64 a, u64 b, u64 c) {
    u64 d; asm("fma.rn.f32x2 %0, %1, %2, %3;" : "=l"(d) : "l"(a), "l"(b), "l"(c)); return d;
}

// W tile staging: tile for i is [32 j][128 z] floats (z = d*8+a in global),
// stored transposed to [a][d] per j with float4-XOR swizzle:
// float z' = a*16+d at  phys = j*128 + ((z'>>2) ^ j)*4 + (z'&3).
__device__ __forceinline__ void stage_load(float4* g, const float4* Wg4,
                                           int sj, int sf, int ig) {
#pragma unroll
    for (int k = 0; k < 4; k++) g[k] = Wg4[(sj * II + ig) * 32 + k * 8 + sf];
}
__device__ __forceinline__ void stage_store(float* slot, const float4* g,
                                            int sj, int sq0, int ssub) {
    float* row = slot + sj * 128;
#pragma unroll
    for (int k = 0; k < 4; k++) {
        row[((sq0 + 0  + k) ^ sj) * 4 + ssub] = g[k].x;
        row[((sq0 + 4  + k) ^ sj) * 4 + ssub] = g[k].y;
        row[((sq0 + 8  + k) ^ sj) * 4 + ssub] = g[k].z;
        row[((sq0 + 12 + k) ^ sj) * 4 + ssub] = g[k].w;
    }
}

// ---------------------------------------------------------------------------
// Pass kernel: 144 CTAs (one 32-i chunk, all 32 batches), 256 threads = 8 warps.
// lane = j; warp w owns batches 4w..4w+3.
// Dynamic shared (98304 B):
//   [0, 16384)      W ring: 4 slots x 4096 floats (slot = il & 3)
//   [16384, 24576)  x full chunk: xsh[b*256 + il*8 + a]
// ---------------------------------------------------------------------------
template <int PASS>
__global__ void __launch_bounds__(256, 1)
pass_kernel(const float* __restrict__ xg, const float* __restrict__ Wg) {
    extern __shared__ float sh[];
    float* xsh = sh + 16384;
    const float4* Wg4 = (const float4*)Wg;

    const int t  = threadIdx.x;
    const int j  = t & 31;         // lane = output capsule
    const int w  = t >> 5;         // warp 0..7
    const int b0 = w * 4;
    const int i0 = blockIdx.x * CHUNK;
    // staging: thread -> (row sj, col group sf)
    const int sj   = t >> 3;       // 0..31
    const int sf   = t & 7;
    const int ssub = sf >> 1;
    const int sq0  = (sf & 1) << 4;

    // v history packed as (v[2dp], v[2dp+1])
    u64 v2[4][DD / 2];
    if (PASS > 0) {
#pragma unroll
        for (int bi = 0; bi < 4; bi++) {
            const u64* vp = (const u64*)&g_vsum[((b0 + bi) * JJ + j) * DD];
#pragma unroll
            for (int dp = 0; dp < DD / 2; dp++) v2[bi][dp] = vp[dp];
        }
    }

    // x: full chunk, contiguous 256 floats per b
    for (int idx = t; idx < 8192; idx += 256) {
        int b = idx >> 8;
        xsh[idx] = xg[b * (II * DA) + i0 * DA + (idx & 255)];
    }

    // prologue: fill slots 0,1; prefetch i0+2 into regs
    float4 g[4];
    stage_load(g, Wg4, sj, sf, i0 + 0);
    stage_store(sh + ((0 & 3) << 12), g, sj, sq0, ssub);
    stage_load(g, Wg4, sj, sf, i0 + 1);
    stage_store(sh + ((1 & 3) << 12), g, sj, sq0, ssub);
    stage_load(g, Wg4, sj, sf, i0 + 2);
    __syncthreads();

    u64 acc2[4][DD / 2];
#pragma unroll
    for (int bi = 0; bi < 4; bi++)
#pragma unroll
        for (int dp = 0; dp < DD / 2; dp++) acc2[bi][dp] = 0ull;

    auto compute = [&](int il) {
        const ulonglong2* wb = (const ulonglong2*)(sh + ((il & 3) << 12) + j * 128);
        const float* xb = xsh + il * 8;

        u64 u2[4][DD / 2];
        if (PASS > 0) {
#pragma unroll
            for (int bi = 0; bi < 4; bi++)
#pragma unroll
                for (int dp = 0; dp < DD / 2; dp++) u2[bi][dp] = 0ull;
        }

#pragma unroll
        for (int a = 0; a < DA; a++) {
            u64 xx[4];
#pragma unroll
            for (int bi = 0; bi < 4; bi++) {
                float xv = xb[(b0 + bi) * 256 + a];     // broadcast LDS
                xx[bi] = pack2(xv, xv);
            }
#pragma unroll
            for (int d4 = 0; d4 < 4; d4++) {
                ulonglong2 wv = wb[((a << 2) | d4) ^ j]; // conflict-free LDS.128
#pragma unroll
                for (int bi = 0; bi < 4; bi++) {
                    if (PASS == 0) {  // uniform c folded into squash round 0
                        acc2[bi][2 * d4]     = ffma2(wv.x, xx[bi], acc2[bi][2 * d4]);
                        acc2[bi][2 * d4 + 1] = ffma2(wv.y, xx[bi], acc2[bi][2 * d4 + 1]);
                    } else {
                        u2[bi][2 * d4]     = ffma2(wv.x, xx[bi], u2[bi][2 * d4]);
                        u2[bi][2 * d4 + 1] = ffma2(wv.y, xx[bi], u2[bi][2 * d4 + 1]);
                    }
                }
            }
        }

        if (PASS > 0) {
#pragma unroll
            for (int bi = 0; bi < 4; bi++) {
                u64 lp = 0ull;
#pragma unroll
                for (int dp = 0; dp < DD / 2; dp++)
                    lp = ffma2(u2[bi][dp], v2[bi][dp], lp);
                float lo, hi; unpack2(lp, lo, hi);
                // softmax over j = lanes; logits bounded -> skip max-subtract
                float e = __expf(lo + hi);
                float z = e;
#pragma unroll
                for (int off = 16; off > 0; off >>= 1)
                    z += __shfl_xor_sync(0xffffffffu, z, off);
                float c = __fdividef(e, z);
                u64 cc = pack2(c, c);
#pragma unroll
                for (int dp = 0; dp < DD / 2; dp++)
                    acc2[bi][dp] = ffma2(cc, u2[bi][dp], acc2[bi][dp]);
            }
        }
    };

    for (int pp = 0; pp < CHUNK / 2; ++pp) {
        const int il0 = 2 * pp;
        compute(il0);
        if (pp + 1 < CHUNK / 2) {
            // slot (il0+2)&3 last read at il0-2 (before previous barrier) -> safe
            stage_store(sh + (((il0 + 2) & 3) << 12), g, sj, sq0, ssub);
            stage_load(g, Wg4, sj, sf, i0 + il0 + 3);
        }
        compute(il0 + 1);
        if (pp + 1 < CHUNK / 2) {
            stage_store(sh + (((il0 + 3) & 3) << 12), g, sj, sq0, ssub);
            if (pp + 2 < CHUNK / 2)
                stage_load(g, Wg4, sj, sf, i0 + il0 + 4);
            __syncthreads();
        }
    }

    // per-chunk partials (deterministic two-stage reduction)
#pragma unroll
    for (int bi = 0; bi < 4; bi++) {
        u64* p = (u64*)&g_partial[((blockIdx.x * BB + (b0 + bi)) * JJ + j) * DD];
#pragma unroll
        for (int dp = 0; dp < DD / 2; dp++) p[dp] = acc2[bi][dp];
    }
}

// ---------------------------------------------------------------------------
// Squash: 64 CTAs x 1024 threads. Each output handled by 4 threads (36 chunks
// each, 4-way ILP), combined in shared, then 16-lane shfl for |s|^2.
// ---------------------------------------------------------------------------
template <int ROUND>
__global__ void __launch_bounds__(1024)
squash_kernel(float* __restrict__ out) {
    __shared__ float red[1024];
    const int o = (int)blockIdx.x * 256 + (threadIdx.x & 255);  // output index
    const int q = threadIdx.x >> 8;                             // chunk slice 0..3

    const float* p = g_partial + q * 36 * OUTSZ + o;
    float s0 = 0.f, s1 = 0.f, s2 = 0.f, s3 = 0.f;
#pragma unroll
    for (int c = 0; c < 36; c += 4) {
        s0 += p[(c + 0) * OUTSZ];
        s1 += p[(c + 1) * OUTSZ];
        s2 += p[(c + 2) * OUTSZ];
        s3 += p[(c + 3) * OUTSZ];
    }
    red[threadIdx.x] = (s0 + s1) + (s2 + s3);
    __syncthreads();

    if (q == 0) {
        int tt = threadIdx.x;  // 0..255
        float s = (red[tt] + red[tt + 256]) + (red[tt + 512] + red[tt + 768]);
        if (ROUND == 0) s *= 0.03125f;  // uniform c = 1/32 folded here

        float sq = s * s;  // lanes d=0..15 form aligned 16-groups within warp
#pragma unroll
        for (int off = 8; off > 0; off >>= 1)
            sq += __shfl_xor_sync(0xffffffffu, sq, off);

        float v = s * (sq / ((1.0f + sq) * sqrtf(sq + CAP_EPS)));

        if (ROUND == 0)      g_vsum[o] = v;
        else if (ROUND == 1) g_vsum[o] += v;
        else                 out[o] = v;
    }
}

// ---------------------------------------------------------------------------
extern "C" void kernel_launch(void* const* d_in, const int* in_sizes, int n_in,
                              void* d_out, int out_size) {
    (void)in_sizes; (void)n_in; (void)out_size;
    const float* xg = (const float*)d_in[0];   // inputs [32,4608,8]
    const float* Wg = (const float*)d_in[1];   // W      [32,4608,16,8]
    float* out = (float*)d_out;                // [32,32,16]

    const int SMEM = 98304;  // 96 KB dynamic -> needs opt-in (idempotent, host-side)
    cudaFuncSetAttribute(pass_kernel<0>, cudaFuncAttributeMaxDynamicSharedMemorySize, SMEM);
    cudaFuncSetAttribute(pass_kernel<1>, cudaFuncAttributeMaxDynamicSharedMemorySize, SMEM);
    cudaFuncSetAttribute(pass_kernel<2>, cudaFuncAttributeMaxDynamicSharedMemorySize, SMEM);

    pass_kernel<0><<<NCHUNK, 256, SMEM>>>(xg, Wg);
    squash_kernel<0><<<64, 1024>>>(out);
    pass_kernel<1><<<NCHUNK, 256, SMEM>>>(xg, Wg);
    squash_kernel<1><<<64, 1024>>>(out);
    pass_kernel<2><<<NCHUNK, 256, SMEM>>>(xg, Wg);
    squash_kernel<2><<<64, 1024>>>(out);
}